// round 5
// baseline (speedup 1.0000x reference)
#include <cuda_runtime.h>

#define LSEQ  2048
#define BATCH 512
#define IN    78
#define NG    16

#define NSCAN_BLK   32            // 16 batches per block (2 pairs x 8)
#define NGEMM_BLK   8192          // 128 rows each, 4 blocks per timestep
#define BLK_PER_SLAB 64           // 64 gemm blocks = 16 timesteps
#define NSLAB       128           // 8192 / 64
#define KCH 8                     // timesteps per chunk (ring granule)
#define NCH (LSEQ / KCH)          // 256 chunks

// 64 MiB scratch for precomputed, prescaled input gates, layout [t][b][u*4+e]
__device__ float g_xg[LSEQ * BATCH * NG];
__device__ int   g_ready[NSLAB];

__device__ __forceinline__ float tanhf_a(float x) {
    float r; asm("tanh.approx.f32 %0, %1;" : "=f"(r) : "f"(x)); return r;
}
__device__ __forceinline__ int ld_acq(const int* p) {
    int v; asm volatile("ld.acquire.gpu.global.b32 %0, [%1];" : "=r"(v) : "l"(p)); return v;
}
__device__ __forceinline__ void barsync64(int id) {
    asm volatile("bar.sync %0, 64;" :: "r"(id) : "memory");
}

// sigmoid(x) = 0.5 + 0.5*tanh(0.5*x) -> prescale sigmoid-gate rows by 0.5
__global__ void reset_kernel() {
    if (threadIdx.x < NSLAB) g_ready[threadIdx.x] = 0;
}

// ---------------------------------------------------------------------------
// GEMM producer: one block = 128 (t,b) rows of xg.
// xg[t][b][u*4+e] = scale_e * ( x[t][b] . W_ih0[e*4+u] + b_ih0 + b_hh0 )
// scale_e = 0.5 for sigmoid gates (e=0,1,3), 1.0 for the tanh gate (e=2).
// ---------------------------------------------------------------------------
__device__ __forceinline__ void gemm_block(
    int gbid,
    const float* __restrict__ x,
    const float* __restrict__ Wih0,
    const float* __restrict__ bih0,
    const float* __restrict__ bhh0)
{
    __shared__ float xs[128 * 79];
    __shared__ float ws[IN * NG];
    __shared__ float bs[NG];

    const int tid = threadIdx.x;
    const int rowbase = gbid * 128;
    const float* xsrc = x + rowbase * IN;

    for (int i = tid; i < 128 * IN; i += 256) {
        int r = i / IN;
        int d = i - r * IN;
        xs[r * 79 + d] = xsrc[i];
    }
    for (int i = tid; i < IN * NG; i += 256) {
        int d = i >> 4, n = i & 15;
        int u = n >> 2, e = n & 3;
        float sc = (e == 2) ? 1.0f : 0.5f;
        ws[i] = Wih0[(e * 4 + u) * IN + d] * sc;
    }
    if (tid < NG) {
        int u = tid >> 2, e = tid & 3;
        float sc = (e == 2) ? 1.0f : 0.5f;
        bs[tid] = (bih0[e * 4 + u] + bhh0[e * 4 + u]) * sc;
    }
    __syncthreads();

    const int r  = tid & 127;
    const int n0 = (tid >> 7) * 8;

    float acc0 = bs[n0 + 0], acc1 = bs[n0 + 1], acc2 = bs[n0 + 2], acc3 = bs[n0 + 3];
    float acc4 = bs[n0 + 4], acc5 = bs[n0 + 5], acc6 = bs[n0 + 6], acc7 = bs[n0 + 7];

    const float* xrow = xs + r * 79;
    #pragma unroll 13
    for (int d = 0; d < IN; d++) {
        float xv = xrow[d];
        float4 wa = *(const float4*)(ws + d * NG + n0);
        float4 wb = *(const float4*)(ws + d * NG + n0 + 4);
        acc0 = fmaf(xv, wa.x, acc0);
        acc1 = fmaf(xv, wa.y, acc1);
        acc2 = fmaf(xv, wa.z, acc2);
        acc3 = fmaf(xv, wa.w, acc3);
        acc4 = fmaf(xv, wb.x, acc4);
        acc5 = fmaf(xv, wb.y, acc5);
        acc6 = fmaf(xv, wb.z, acc6);
        acc7 = fmaf(xv, wb.w, acc7);
    }

    float4* outp = (float4*)(g_xg + (rowbase + r) * NG + n0);
    outp[0] = make_float4(acc0, acc1, acc2, acc3);
    outp[1] = make_float4(acc4, acc5, acc6, acc7);

    __syncthreads();
    if (tid == 0) {
        __threadfence();
        atomicAdd(&g_ready[gbid >> 6], 1);
    }
}

// ---------------------------------------------------------------------------
// Scan: warp-specialized layer pipeline.
//   warps 0,2: layer0 for 8 batches each (lane = bl*4 + u)
//   warps 1,3: layer1 for the same batches, one chunk (8 steps) behind,
//              reading h0 from a double-buffered smem ring.
// Chunk protocol (per pair, named barrier id = pair+1, count 64):
//   iter c: bar; L0 computes steps [8c,8c+8) -> ring[c&1];
//           L1 computes steps [8(c-1),8c) from ring[(c-1)&1].
// Activations: tanh.approx; sigmoid gates prescaled by 0.5 (GEMM + weights).
// ---------------------------------------------------------------------------
__device__ __forceinline__ void scan_block(
    const float* __restrict__ Whh0,
    const float* __restrict__ Wih1,
    const float* __restrict__ Whh1,
    const float* __restrict__ bih1,
    const float* __restrict__ bhh1,
    const int*   __restrict__ lens,
    float*       __restrict__ out)
{
    __shared__ __align__(16) float ring[2][2][KCH][32];

    const int tid = threadIdx.x;
    if (tid >= 128) return;
    const int wid   = tid >> 5;
    const int lane  = tid & 31;
    const int pair  = wid >> 1;
    const bool isL0 = (wid & 1) == 0;
    const int barid = pair + 1;
    const int u     = lane & 3;
    const int gb    = lane & ~3;             // 4-lane unit-group base
    const int b     = blockIdx.x * 16 + pair * 8 + (lane >> 2);

    if (isL0) {
        // -------- layer 0 producer --------
        float w[4][4];
        #pragma unroll
        for (int e = 0; e < 4; e++) {
            const float sc = (e == 2) ? 1.0f : 0.5f;
            #pragma unroll
            for (int k = 0; k < 4; k++)
                w[e][k] = Whh0[(e * 4 + u) * 4 + k] * sc;
        }

        float h = 0.0f, c = 0.0f;
        const float4* xg4 = (const float4*)g_xg;
        const int bidx = b * 4 + u;

        while (ld_acq(&g_ready[0]) < BLK_PER_SLAB) __nanosleep(64);
        float4 buf[4];
        #pragma unroll
        for (int j = 0; j < 4; j++)
            buf[j] = xg4[j * (BATCH * 4) + bidx];

        for (int cch = 0; cch <= NCH; cch++) {
            barsync64(barid);
            if (cch == NCH) break;
            float* rb = &ring[pair][cch & 1][0][0];

            #pragma unroll
            for (int q = 0; q < 2; q++) {
                const int t0 = cch * KCH + q * 4;
                if ((t0 & 15) == 0) {
                    int s = (t0 >> 4) + 1;
                    s = (s > NSLAB - 1) ? (NSLAB - 1) : s;
                    while (ld_acq(&g_ready[s]) < BLK_PER_SLAB) __nanosleep(64);
                }
                float4 nbuf[4];
                #pragma unroll
                for (int j = 0; j < 4; j++) {
                    int t = t0 + 4 + j;
                    t = (t > LSEQ - 1) ? (LSEQ - 1) : t;
                    nbuf[j] = xg4[t * (BATCH * 4) + bidx];
                }

                #pragma unroll
                for (int j = 0; j < 4; j++) {
                    float a0 = __shfl_sync(0xffffffffu, h, gb + 0);
                    float a1 = __shfl_sync(0xffffffffu, h, gb + 1);
                    float a2 = __shfl_sync(0xffffffffu, h, gb + 2);
                    float a3 = __shfl_sync(0xffffffffu, h, gb + 3);

                    float xb[4];
                    xb[0] = buf[j].x; xb[1] = buf[j].y;
                    xb[2] = buf[j].z; xb[3] = buf[j].w;

                    float tt[4];
                    #pragma unroll
                    for (int e = 0; e < 4; e++) {
                        float m01 = fmaf(a1, w[e][1], a0 * w[e][0]);
                        float m23 = fmaf(a3, w[e][3], a2 * w[e][2]);
                        tt[e] = tanhf_a((xb[e] + m01) + m23);
                    }
                    float A  = fmaf(tt[1], c, c);
                    float Bv = fmaf(tt[0], tt[2], tt[2]);
                    float cn = 0.5f * (A + Bv);
                    float tc = tanhf_a(cn);
                    h = 0.5f * fmaf(tt[3], tc, tc);
                    c = cn;
                    rb[(q * 4 + j) * 32 + lane] = h;
                }
                buf[0] = nbuf[0]; buf[1] = nbuf[1];
                buf[2] = nbuf[2]; buf[3] = nbuf[3];
            }
        }
    } else {
        // -------- layer 1 consumer --------
        float v[4][4], w[4][4], bias[4];
        #pragma unroll
        for (int e = 0; e < 4; e++) {
            const float sc = (e == 2) ? 1.0f : 0.5f;
            const int row = e * 4 + u;
            bias[e] = (bih1[row] + bhh1[row]) * sc;
            #pragma unroll
            for (int k = 0; k < 4; k++) {
                v[e][k] = Wih1[row * 4 + k] * sc;
                w[e][k] = Whh1[row * 4 + k] * sc;
            }
        }
        const int len = lens[b];
        float h = 0.0f, c = 0.0f;
        float* outb = out + b * 4 + u;

        for (int cch = 0; cch <= NCH; cch++) {
            barsync64(barid);
            if (cch == 0) continue;
            const float* rb = &ring[pair][(cch - 1) & 1][0][0];
            const int tb = (cch - 1) * KCH;

            float4 P = *(const float4*)(rb + gb);
            #pragma unroll
            for (int j = 0; j < KCH; j++) {
                const int jn = (j < KCH - 1) ? (j + 1) : j;
                float4 Pn = *(const float4*)(rb + jn * 32 + gb);

                float a0 = __shfl_sync(0xffffffffu, h, gb + 0);
                float a1 = __shfl_sync(0xffffffffu, h, gb + 1);
                float a2 = __shfl_sync(0xffffffffu, h, gb + 2);
                float a3 = __shfl_sync(0xffffffffu, h, gb + 3);

                float tt[4];
                #pragma unroll
                for (int e = 0; e < 4; e++) {
                    // h0-dot + bias: off the critical chain (P prefetched)
                    float pe = fmaf(P.y, v[e][1], fmaf(P.x, v[e][0], bias[e]));
                    pe = fmaf(P.w, v[e][3], fmaf(P.z, v[e][2], pe));
                    float n01 = fmaf(a1, w[e][1], a0 * w[e][0]);
                    float n23 = fmaf(a3, w[e][3], a2 * w[e][2]);
                    tt[e] = tanhf_a((pe + n01) + n23);
                }
                float A  = fmaf(tt[1], c, c);
                float Bv = fmaf(tt[0], tt[2], tt[2]);
                float cn = 0.5f * (A + Bv);
                float tc = tanhf_a(cn);
                h = 0.5f * fmaf(tt[3], tc, tc);
                c = cn;

                const int t = tb + j;
                outb[t * (BATCH * 4)] = (t < len) ? h : 0.0f;
                P = Pn;
            }
        }
    }
}

// ---------------------------------------------------------------------------
// Fused kernel: blocks 0..31 = scan (wave 1 resident), rest = gemm.
// ---------------------------------------------------------------------------
__global__ void __launch_bounds__(256) fused_kernel(
    const float* __restrict__ x,
    const float* __restrict__ Wih0,
    const float* __restrict__ bih0,
    const float* __restrict__ bhh0,
    const float* __restrict__ Whh0,
    const float* __restrict__ Wih1,
    const float* __restrict__ Whh1,
    const float* __restrict__ bih1,
    const float* __restrict__ bhh1,
    const int*   __restrict__ lens,
    float*       __restrict__ out)
{
    if (blockIdx.x < NSCAN_BLK) {
        scan_block(Whh0, Wih1, Whh1, bih1, bhh1, lens, out);
    } else {
        gemm_block(blockIdx.x - NSCAN_BLK, x, Wih0, bih0, bhh0);
    }
}

extern "C" void kernel_launch(void* const* d_in, const int* in_sizes, int n_in,
                              void* d_out, int out_size)
{
    const float* x    = (const float*)d_in[0];
    const int*   lens = (const int*)  d_in[1];
    const float* Wih0 = (const float*)d_in[2];
    const float* Whh0 = (const float*)d_in[3];
    const float* bih0 = (const float*)d_in[4];
    const float* bhh0 = (const float*)d_in[5];
    const float* Wih1 = (const float*)d_in[6];
    const float* Whh1 = (const float*)d_in[7];
    const float* bih1 = (const float*)d_in[8];
    const float* bhh1 = (const float*)d_in[9];
    float* out = (float*)d_out;

    reset_kernel<<<1, 128>>>();
    fused_kernel<<<NSCAN_BLK + NGEMM_BLK, 256>>>(
        x, Wih0, bih0, bhh0, Whh0, Wih1, Whh1, bih1, bhh1, lens, out);
}